// round 1
// baseline (speedup 1.0000x reference)
#include <cuda_runtime.h>
#include <math.h>

#define Bn 8
#define Cn 256
#define Ln 1024
#define MCn 64
#define DIn 128
#define Kn 4
#define Nn 16
#define EPSf 1e-5f

// ---------------- scratch (device globals; no allocation allowed) ----------------
__device__ float g_x [Bn*Ln*MCn];      // post-bn x, (b,l,o) pixel-major
__device__ float g_z [Bn*Ln*DIn];      // gate z, (b,l,d)
__device__ float g_x1[Bn*DIn*Ln];      // pre-conv x1, (b,d,l)
__device__ float g_u [Bn*DIn*Ln];      // post conv+silu, (b,d,l)
__device__ float g_M [Kn*Bn*36*Ln];    // x_proj outputs per direction weight, (k,b,c,l)
__device__ float g_dt[Kn*Bn*DIn*Ln];   // softplus(dt), (k,b,d,l)  [spatial l]
__device__ float g_Bt[Kn*Bn*Ln*Nn];    // B transposed, (k,b,l,n)
__device__ float g_Ct[Kn*Bn*Ln*Nn];    // C transposed, (k,b,l,n)
__device__ float g_y [Bn*DIn*Ln];      // combined scan output, (b,d,l)
__device__ float g_zr[Bn*Cn];
__device__ float g_zd[Bn*Cn];
__device__ float g_zm[Bn*MCn];
__device__ float g_wgt[Bn*2*Cn];

// ---------------- K0: zero z_mamba accumulator ----------------
__global__ void k0_init(){
    int i = blockIdx.x*256 + threadIdx.x;
    if(i < Bn*MCn) g_zm[i] = 0.f;
}

// ---------------- K1: x = bn(w_reduce @ (rgb+dem)) ----------------
// grid (32, 8), 256 thr, dyn smem = (64*256 + 256*32)*4 = 98304 B
__global__ void k1_reduce(const float* __restrict__ rgb, const float* __restrict__ dem,
                          const float* __restrict__ wr,  const float* __restrict__ bg,
                          const float* __restrict__ bb,  const float* __restrict__ bm,
                          const float* __restrict__ bv){
    extern __shared__ float sh[];
    float* shW = sh;              // [64][256]
    float* shX = sh + 64*256;     // [256][32]  (c, l)
    int b  = blockIdx.y;
    int l0 = blockIdx.x*32;
    int tid = threadIdx.x;
    for(int i=tid;i<64*256;i+=256) shW[i]=wr[i];
    for(int i=tid;i<256*32;i+=256){
        int c=i>>5, l=i&31;
        int gi=(b*Cn+c)*Ln + l0 + l;
        shX[i]=rgb[gi]+dem[gi];
    }
    __syncthreads();
    int l = tid & 31, o8 = tid>>5;   // 8 o-groups x 32 l
    float acc[8]={0,0,0,0,0,0,0,0};
    for(int c=0;c<256;c++){
        float xv = shX[c*32+l];
        #pragma unroll
        for(int j=0;j<8;j++) acc[j]=fmaf(shW[(o8*8+j)*256+c],xv,acc[j]);
    }
    #pragma unroll
    for(int j=0;j<8;j++){
        int o=o8*8+j;
        float v=(acc[j]-bm[o])*rsqrtf(bv[o]+EPSf)*bg[o]+bb[o];
        g_x[(b*Ln+l0+l)*MCn + o]=v;
    }
}

// ---------------- K2: ln1 + in_proj -> x1(pre-conv), z ----------------
// grid (64, 8), 256 thr, dyn smem = (256*64 + 16*65)*4 = 69696 B
__global__ void k2_lnproj(const float* __restrict__ lg, const float* __restrict__ lb,
                          const float* __restrict__ ipw){
    extern __shared__ float sh[];
    float* shW  = sh;             // [256][64]
    float* shXn = sh + 256*64;    // [16][65]
    int b  = blockIdx.y;
    int l0 = blockIdx.x*16;
    int tid = threadIdx.x;
    for(int i=tid;i<256*64;i+=256) shW[i]=ipw[i];
    int w = tid>>5, lane = tid&31;
    #pragma unroll
    for(int pp=0;pp<2;pp++){
        int p=w*2+pp;
        const float* xr = g_x + (b*Ln + l0+p)*MCn;
        float v0=xr[lane], v1=xr[lane+32];
        float s=v0+v1, s2=v0*v0+v1*v1;
        #pragma unroll
        for(int off=16;off>0;off>>=1){
            s  += __shfl_xor_sync(0xffffffffu,s ,off);
            s2 += __shfl_xor_sync(0xffffffffu,s2,off);
        }
        float mean=s*(1.f/64.f);
        float var =s2*(1.f/64.f)-mean*mean;
        float rs=rsqrtf(var+EPSf);
        shXn[p*65+lane]    =(v0-mean)*rs*lg[lane]   +lb[lane];
        shXn[p*65+lane+32] =(v1-mean)*rs*lg[lane+32]+lb[lane+32];
    }
    __syncthreads();
    int og = tid>>4, l = tid&15;   // 16 out-groups x 16 pixels
    float acc[16];
    #pragma unroll
    for(int j=0;j<16;j++) acc[j]=0.f;
    for(int c=0;c<64;c++){
        float xv=shXn[l*65+c];
        #pragma unroll
        for(int j=0;j<16;j++) acc[j]=fmaf(shW[(og*16+j)*64+c],xv,acc[j]);
    }
    #pragma unroll
    for(int j=0;j<16;j++){
        int o=og*16+j;
        if(o<DIn) g_x1[(b*DIn+o)*Ln + l0+l]=acc[j];
        else      g_z [(b*Ln+l0+l)*DIn + (o-DIn)]=acc[j];
    }
}

// ---------------- K3: depthwise conv3x3 SAME + bias + silu ----------------
__global__ void k3_conv(const float* __restrict__ cw, const float* __restrict__ cb){
    int idx = blockIdx.x*256 + threadIdx.x;
    if(idx >= Bn*DIn*Ln) return;
    int l = idx & 1023;
    int d = (idx>>10)&127;
    int h = l>>5, w2 = l&31;
    const float* src = g_x1 + (idx & ~1023);
    const float* cwd = cw + d*9;
    float acc = cb[d];
    #pragma unroll
    for(int kh=0;kh<3;kh++){
        int hh=h+kh-1;
        if((unsigned)hh<32u){
            #pragma unroll
            for(int kw=0;kw<3;kw++){
                int ww=w2+kw-1;
                if((unsigned)ww<32u) acc=fmaf(src[hh*32+ww],cwd[kh*3+kw],acc);
            }
        }
    }
    g_u[idx]=acc/(1.f+__expf(-acc));
}

// ---------------- K4a: M[k,b,c,l] = sum_d x_proj_w[k,c,d] * u[b,d,l] ----------------
// grid (16, 8), 256 thr, dyn smem = (128*64 + 144*128)*4 = 106496 B
__global__ void k4a_proj(const float* __restrict__ xpw){
    extern __shared__ float sh[];
    float* shU = sh;              // [128][64] (d,l)
    float* shW = sh + 128*64;     // [144][128]
    int b  = blockIdx.y;
    int l0 = blockIdx.x*64;
    int tid = threadIdx.x;
    for(int i=tid;i<144*128;i+=256) shW[i]=xpw[i];
    for(int i=tid;i<128*64;i+=256){
        int d=i>>6, l=i&63;
        shU[i]=g_u[(b*DIn+d)*Ln + l0+l];
    }
    __syncthreads();
    int l = tid&63, k = tid>>6;   // one direction per 64-thread group
    float acc[36];
    #pragma unroll
    for(int j=0;j<36;j++) acc[j]=0.f;
    for(int d=0;d<128;d++){
        float xv=shU[d*64+l];
        #pragma unroll
        for(int j=0;j<36;j++) acc[j]=fmaf(shW[(k*36+j)*128+d],xv,acc[j]);
    }
    #pragma unroll
    for(int j=0;j<36;j++)
        g_M[((k*Bn+b)*36+j)*Ln + l0+l]=acc[j];
}

// ---------------- K4b: dt = softplus(dt_w @ M[:R] + dt_b) ----------------
__global__ void k4b_dt(const float* __restrict__ dtw, const float* __restrict__ dtb){
    int idx=blockIdx.x*256+threadIdx.x;
    if(idx>=Kn*Bn*DIn*Ln) return;
    int l=idx&1023, d=(idx>>10)&127, b=(idx>>17)&7, k=idx>>20;
    const float* Mr = g_M + (k*Bn+b)*36*Ln + l;
    const float* w  = dtw + (k*DIn+d)*4;
    float x = dtb[k*DIn+d];
    #pragma unroll
    for(int r=0;r<4;r++) x=fmaf(Mr[r*Ln],w[r],x);
    g_dt[idx] = (x>20.f) ? x : log1pf(__expf(x));
}

// ---------------- K4c: transpose B,C rows to (k,b,l,n) ----------------
__global__ void k4c_bc(){
    int idx=blockIdx.x*256+threadIdx.x;
    if(idx>=Kn*Bn*Ln*Nn) return;
    int l=idx&1023, n=(idx>>10)&15, b=(idx>>14)&7, k=idx>>17;
    int kb=k*Bn+b;
    float bvv=g_M[(kb*36+ 4+n)*Ln+l];
    float cvv=g_M[(kb*36+20+n)*Ln+l];
    int o=(kb*Ln+l)*Nn+n;
    g_Bt[o]=bvv; g_Ct[o]=cvv;
}

// ---------------- K4d: y init = (sum_k Ds[k,d]) * u ----------------
__global__ void k4d_yinit(const float* __restrict__ Ds){
    int idx=blockIdx.x*256+threadIdx.x;
    if(idx>=Bn*DIn*Ln) return;
    int d=(idx>>10)&127;
    float s=Ds[d]+Ds[DIn+d]+Ds[2*DIn+d]+Ds[3*DIn+d];
    g_y[idx]=s*g_u[idx];
}

// ---------------- K5: selective scan, 4 directions, scatter-accumulate into y ----------------
__device__ __forceinline__ int pmap(int k,int t){
    int tt=(k&2)?(1023-t):t;
    return (k&1)?(((tt&31)<<5)|(tt>>5)):tt;
}
__global__ void k5_scan(const float* __restrict__ Alogs){
    int tid=threadIdx.x;
    int n=tid&15, dl=tid>>4;
    int d=blockIdx.x*16+dl;
    int k=blockIdx.y, b=blockIdx.z;
    float A=-__expf(Alogs[(k*DIn+d)*Nn+n]);
    const float* uP =g_u +(b*DIn+d)*Ln;
    const float* dtP=g_dt+((k*Bn+b)*DIn+d)*Ln;
    const float* BtP=g_Bt+(k*Bn+b)*Ln*Nn;
    const float* CtP=g_Ct+(k*Bn+b)*Ln*Nn;
    float* yP=g_y+(b*DIn+d)*Ln;
    float h=0.f;
    int p=pmap(k,0);
    float dtv=dtP[p], uv=uP[p], Bv=BtP[p*16+n], Cv=CtP[p*16+n];
    for(int t=0;t<1024;t++){
        int pn=pmap(k,(t+1)&1023);
        float dtn=dtP[pn], un=uP[pn], Bn2=BtP[pn*16+n], Cn2=CtP[pn*16+n];
        float a=__expf(dtv*A);
        h=fmaf(h,a,dtv*uv*Bv);
        float c=h*Cv;
        c += __shfl_xor_sync(0xffffffffu,c,8,16);
        c += __shfl_xor_sync(0xffffffffu,c,4,16);
        c += __shfl_xor_sync(0xffffffffu,c,2,16);
        c += __shfl_xor_sync(0xffffffffu,c,1,16);
        if(n==0) atomicAdd(&yP[p],c);
        p=pn; dtv=dtn; uv=un; Bv=Bn2; Cv=Cn2;
    }
}

// ---------------- K6: ln(y)*silu(z) -> out_proj -> +x -> ln(mno) -> mean accumulate ----------------
// warp per pixel; grid 1024 x 256 thr
__global__ void k6_out(const float* __restrict__ ong, const float* __restrict__ onb,
                       const float* __restrict__ opw, const float* __restrict__ mg,
                       const float* __restrict__ mbb){
    __shared__ float sY[8*128];
    int tid=threadIdx.x, w=tid>>5, lane=tid&31;
    int pix=blockIdx.x*8+w;
    int b=pix>>10, l=pix&1023;
    float yv[4], zv[4];
    #pragma unroll
    for(int j=0;j<4;j++){
        int d=lane+32*j;
        yv[j]=g_y[(b*DIn+d)*Ln+l];
        zv[j]=g_z[(b*Ln+l)*DIn+d];
    }
    float s=0.f,s2=0.f;
    #pragma unroll
    for(int j=0;j<4;j++){ s+=yv[j]; s2+=yv[j]*yv[j]; }
    #pragma unroll
    for(int off=16;off>0;off>>=1){
        s  += __shfl_xor_sync(0xffffffffu,s ,off);
        s2 += __shfl_xor_sync(0xffffffffu,s2,off);
    }
    float mean=s*(1.f/128.f);
    float var =s2*(1.f/128.f)-mean*mean;
    float rs=rsqrtf(var+EPSf);
    #pragma unroll
    for(int j=0;j<4;j++){
        int d=lane+32*j;
        float t=(yv[j]-mean)*rs*ong[d]+onb[d];
        float zz=zv[j];
        sY[w*128+d]=t*zz/(1.f+__expf(-zz));
    }
    __syncwarp();
    float a0=0.f,a1=0.f;
    for(int d2=0;d2<128;d2++){
        float yy=sY[w*128+d2];
        a0=fmaf(opw[ lane     *128+d2],yy,a0);
        a1=fmaf(opw[(lane+32)*128+d2],yy,a1);
    }
    const float* xr=g_x+(b*Ln+l)*MCn;
    float x0=xr[lane]+a0, x1v=xr[lane+32]+a1;
    float ss=x0+x1v, ss2=x0*x0+x1v*x1v;
    #pragma unroll
    for(int off=16;off>0;off>>=1){
        ss  += __shfl_xor_sync(0xffffffffu,ss ,off);
        ss2 += __shfl_xor_sync(0xffffffffu,ss2,off);
    }
    float m2=ss*(1.f/64.f);
    float v2=ss2*(1.f/64.f)-m2*m2;
    float rs2=rsqrtf(v2+EPSf);
    float v0=(x0 -m2)*rs2*mg[lane]   +mbb[lane];
    float v1=(x1v-m2)*rs2*mg[lane+32]+mbb[lane+32];
    atomicAdd(&g_zm[b*MCn+lane],    v0*(1.f/1024.f));
    atomicAdd(&g_zm[b*MCn+lane+32], v1*(1.f/1024.f));
}

// ---------------- K7: spatial means of rgb/dem ----------------
__global__ void k7_means(const float* __restrict__ rgb, const float* __restrict__ dem){
    int gw = (blockIdx.x*256+threadIdx.x)>>5;
    int lane=threadIdx.x&31;
    if(gw>=2*Bn*Cn) return;
    int which = (gw>=Bn*Cn);
    int bc = which ? gw-Bn*Cn : gw;
    const float* src=(which?dem:rgb)+bc*Ln;
    float s=0.f;
    for(int i=lane;i<Ln;i+=32) s+=src[i];
    #pragma unroll
    for(int off=16;off>0;off>>=1) s += __shfl_xor_sync(0xffffffffu,s,off);
    if(lane==0) (which?g_zd:g_zr)[bc]=s*(1.f/1024.f);
}

// ---------------- K8: joint-embed MLP -> sigmoid weights ----------------
__global__ void k8_fc(const float* __restrict__ w1,const float* __restrict__ g1,
                      const float* __restrict__ b1,const float* __restrict__ m1,
                      const float* __restrict__ v1,const float* __restrict__ w2){
    __shared__ float shH[64];
    int b=blockIdx.x, tid=threadIdx.x;
    if(tid<64){
        const float* wr=w1+tid*576;
        float a=0.f;
        for(int j=0;j<256;j++) a=fmaf(wr[j],     g_zr[b*256+j],a);
        for(int j=0;j<256;j++) a=fmaf(wr[256+j], g_zd[b*256+j],a);
        for(int j=0;j<64;j++)  a=fmaf(wr[512+j], g_zm[b*64+j],a);
        float h=(a-m1[tid])*rsqrtf(v1[tid]+EPSf)*g1[tid]+b1[tid];
        shH[tid]=h>0.f?h:0.f;
    }
    __syncthreads();
    for(int o=tid;o<512;o+=128){
        float a=0.f;
        const float* wr=w2+o*64;
        #pragma unroll
        for(int c=0;c<64;c++) a=fmaf(wr[c],shH[c],a);
        g_wgt[b*512+o]=1.f/(1.f+__expf(-a));
    }
}

// ---------------- K9: final reweighting ----------------
__global__ void k9_final(const float* __restrict__ rgb,const float* __restrict__ dem,
                         float* __restrict__ out){
    int idx=blockIdx.x*256+threadIdx.x;
    if(idx>=Bn*Cn*Ln) return;
    int c=(idx>>10)&255, b=idx>>18;
    float wrv=g_wgt[b*512+c], wdv=g_wgt[b*512+256+c];
    out[idx]=rgb[idx]*(1.f+wrv)+dem[idx]*(1.f+wdv);
}

// ---------------- launch ----------------
extern "C" void kernel_launch(void* const* d_in, const int* in_sizes, int n_in,
                              void* d_out, int out_size){
    const float* rgb   =(const float*)d_in[0];
    const float* dem   =(const float*)d_in[1];
    const float* wred  =(const float*)d_in[2];
    const float* bnr_g =(const float*)d_in[3];
    const float* bnr_b =(const float*)d_in[4];
    const float* bnr_m =(const float*)d_in[5];
    const float* bnr_v =(const float*)d_in[6];
    const float* ln1_g =(const float*)d_in[7];
    const float* ln1_b =(const float*)d_in[8];
    const float* ipw   =(const float*)d_in[9];
    const float* conv_w=(const float*)d_in[10];
    const float* conv_b=(const float*)d_in[11];
    const float* xpw   =(const float*)d_in[12];
    const float* dt_w  =(const float*)d_in[13];
    const float* dt_b  =(const float*)d_in[14];
    const float* Alogs =(const float*)d_in[15];
    const float* Ds    =(const float*)d_in[16];
    const float* on_g  =(const float*)d_in[17];
    const float* on_b  =(const float*)d_in[18];
    const float* opw   =(const float*)d_in[19];
    const float* mno_g =(const float*)d_in[20];
    const float* mno_b =(const float*)d_in[21];
    const float* je_w1 =(const float*)d_in[22];
    const float* bn1_g =(const float*)d_in[23];
    const float* bn1_b =(const float*)d_in[24];
    const float* bn1_m =(const float*)d_in[25];
    const float* bn1_v =(const float*)d_in[26];
    const float* je_w2 =(const float*)d_in[27];
    float* out=(float*)d_out;

    cudaFuncSetAttribute(k1_reduce, cudaFuncAttributeMaxDynamicSharedMemorySize, 98304);
    cudaFuncSetAttribute(k2_lnproj, cudaFuncAttributeMaxDynamicSharedMemorySize, 69696);
    cudaFuncSetAttribute(k4a_proj,  cudaFuncAttributeMaxDynamicSharedMemorySize, 106496);

    k0_init<<<2,256>>>();
    k7_means<<<512,256>>>(rgb,dem);
    k1_reduce<<<dim3(32,8),256,98304>>>(rgb,dem,wred,bnr_g,bnr_b,bnr_m,bnr_v);
    k2_lnproj<<<dim3(64,8),256,69696>>>(ln1_g,ln1_b,ipw);
    k3_conv<<<(Bn*DIn*Ln)/256,256>>>(conv_w,conv_b);
    k4a_proj<<<dim3(16,8),256,106496>>>(xpw);
    k4b_dt<<<(Kn*Bn*DIn*Ln)/256,256>>>(dt_w,dt_b);
    k4c_bc<<<(Kn*Bn*Ln*Nn)/256,256>>>();
    k4d_yinit<<<(Bn*DIn*Ln)/256,256>>>(Ds);
    k5_scan<<<dim3(8,4,8),256>>>(Alogs);
    k6_out<<<1024,256>>>(on_g,on_b,opw,mno_g,mno_b);
    k8_fc<<<8,128>>>(je_w1,bn1_g,bn1_b,bn1_m,bn1_v,je_w2);
    k9_final<<<(Bn*Cn*Ln)/256,256>>>(rgb,dem,out);
}

// round 5
// speedup vs baseline: 1.5101x; 1.5101x over previous
#include <cuda_runtime.h>
#include <math.h>

#define Bn 8
#define Cn 256
#define Ln 1024
#define MCn 64
#define DIn 128
#define Kn 4
#define Nn 16
#define EPSf 1e-5f

// ---------------- scratch ----------------
__device__ float g_x [Bn*Ln*MCn];      // post-bn x, (b,l,o)
__device__ float g_z [Bn*Ln*DIn];      // gate z, (b,l,d)
__device__ float g_x1[Bn*DIn*Ln];      // pre-conv, (b,d,l)
__device__ float g_u [Bn*DIn*Ln];      // post conv+silu, (b,d,l)
__device__ float g_ut[Bn*DIn*Ln];      // transposed u: ut[t]=u[tr(t)]
__device__ float g_M [Kn*Bn*36*Ln];    // x_proj out, (k,b,c,l) spatial
__device__ float g_dt[Kn*Bn*DIn*Ln];   // softplus dt in SEQ-TIME order
__device__ float g_Bt[Kn*Bn*Ln*Nn];    // B in seq-time order, (kb,t,n)
__device__ float g_Ct[Kn*Bn*Ln*Nn];    // C in seq-time order
__device__ float g_yP[Bn*Ln*DIn];      // y pixel-major (b,l,d)
__device__ float g_zr[Bn*Cn];
__device__ float g_zd[Bn*Cn];
__device__ float g_zm[Bn*MCn];
__device__ float g_wgt[Bn*2*Cn];

__device__ __forceinline__ int trl(int l){ return ((l&31)<<5)|(l>>5); }
// l = p(k,t): spatial position of sequence step t
__device__ __forceinline__ int pmap(int k,int t){
    int tt=(k&2)?(1023-t):t;
    return (k&1)?trl(tt):tt;
}

// ---------------- K7: spatial means of rgb/dem + zero zm ----------------
__global__ void k7_means(const float* __restrict__ rgb, const float* __restrict__ dem){
    int gid = blockIdx.x*256+threadIdx.x;
    if(gid < Bn*MCn) g_zm[gid]=0.f;
    int gw = gid>>5;
    int lane=threadIdx.x&31;
    if(gw>=2*Bn*Cn) return;
    int which = (gw>=Bn*Cn);
    int bc = which ? gw-Bn*Cn : gw;
    const float* src=(which?dem:rgb)+bc*Ln;
    float s=0.f;
    for(int i=lane;i<Ln;i+=32) s+=src[i];
    #pragma unroll
    for(int off=16;off>0;off>>=1) s += __shfl_xor_sync(0xffffffffu,s,off);
    if(lane==0) (which?g_zd:g_zr)[bc]=s*(1.f/1024.f);
}

// ---------------- K1: x = bn(w_reduce @ (rgb+dem)) ----------------
__global__ void k1_reduce(const float* __restrict__ rgb, const float* __restrict__ dem,
                          const float* __restrict__ wr,  const float* __restrict__ bg,
                          const float* __restrict__ bb,  const float* __restrict__ bm,
                          const float* __restrict__ bv){
    extern __shared__ float sh[];
    float* shW = sh;              // [64][256]
    float* shX = sh + 64*256;     // [256][32]
    int b  = blockIdx.y;
    int l0 = blockIdx.x*32;
    int tid = threadIdx.x;
    for(int i=tid;i<64*256;i+=256) shW[i]=wr[i];
    for(int i=tid;i<256*32;i+=256){
        int c=i>>5, l=i&31;
        int gi=(b*Cn+c)*Ln + l0 + l;
        shX[i]=rgb[gi]+dem[gi];
    }
    __syncthreads();
    int l = tid & 31, o8 = tid>>5;
    float acc[8]={0,0,0,0,0,0,0,0};
    for(int c=0;c<256;c++){
        float xv = shX[c*32+l];
        #pragma unroll
        for(int j=0;j<8;j++) acc[j]=fmaf(shW[(o8*8+j)*256+c],xv,acc[j]);
    }
    #pragma unroll
    for(int j=0;j<8;j++){
        int o=o8*8+j;
        float v=(acc[j]-bm[o])*rsqrtf(bv[o]+EPSf)*bg[o]+bb[o];
        g_x[(b*Ln+l0+l)*MCn + o]=v;
    }
}

// ---------------- K2: ln1 + in_proj -> x1, z ; zero yP ----------------
// grid (32,8), 256 thr, dyn smem = (16384 + 32*68)*4 = 74240 B
__global__ void k2_lnproj(const float* __restrict__ lg, const float* __restrict__ lb,
                          const float* __restrict__ ipw){
    extern __shared__ float sh[];
    float* shW  = sh;             // [256][64]
    float* shXn = sh + 16384;     // [32][68]
    int b  = blockIdx.y;
    int l0 = blockIdx.x*32;
    int tid = threadIdx.x;
    for(int i=tid;i<16384;i+=256) shW[i]=ipw[i];
    for(int i=tid;i<32*128;i+=256) g_yP[(b*Ln+l0)*DIn + i]=0.f;
    int w = tid>>5, lane = tid&31;
    #pragma unroll
    for(int pp=0;pp<4;pp++){
        int p=w*4+pp;
        const float* xr = g_x + (b*Ln + l0+p)*MCn;
        float v0=xr[lane], v1=xr[lane+32];
        float s=v0+v1, s2=v0*v0+v1*v1;
        #pragma unroll
        for(int off=16;off>0;off>>=1){
            s  += __shfl_xor_sync(0xffffffffu,s ,off);
            s2 += __shfl_xor_sync(0xffffffffu,s2,off);
        }
        float mean=s*(1.f/64.f);
        float var =s2*(1.f/64.f)-mean*mean;
        float rs=rsqrtf(var+EPSf);
        shXn[p*68+lane]    =(v0-mean)*rs*lg[lane]   +lb[lane];
        shXn[p*68+lane+32] =(v1-mean)*rs*lg[lane+32]+lb[lane+32];
    }
    __syncthreads();
    int og = tid>>4, pl = tid&15;
    float acc0[16], acc1[16];
    #pragma unroll
    for(int j=0;j<16;j++){ acc0[j]=0.f; acc1[j]=0.f; }
    for(int c=0;c<64;c+=4){
        float4 xa=*(float4*)&shXn[pl*68+c];
        float4 xb=*(float4*)&shXn[(pl+16)*68+c];
        #pragma unroll
        for(int j=0;j<16;j++){
            float4 wv=*(float4*)&shW[(og*16+j)*64+c];
            float t0=fmaf(wv.x,xa.x,fmaf(wv.y,xa.y,fmaf(wv.z,xa.z,wv.w*xa.w)));
            float t1=fmaf(wv.x,xb.x,fmaf(wv.y,xb.y,fmaf(wv.z,xb.z,wv.w*xb.w)));
            acc0[j]+=t0; acc1[j]+=t1;
        }
    }
    __syncthreads();   // shW free now
    float* zb = sh;    // [32][128]
    if(og<8){
        #pragma unroll
        for(int j=0;j<16;j++){
            int o=og*16+j;
            g_x1[(b*DIn+o)*Ln + l0+pl]   = acc0[j];
            g_x1[(b*DIn+o)*Ln + l0+pl+16]= acc1[j];
        }
    } else {
        #pragma unroll
        for(int j=0;j<16;j++){
            int dz=(og-8)*16+j;
            zb[pl*128+dz]     = acc0[j];
            zb[(pl+16)*128+dz]= acc1[j];
        }
    }
    __syncthreads();
    for(int i=tid;i<32*128;i+=256) g_z[(b*Ln+l0)*DIn + i]=zb[i];
}

// ---------------- K3: depthwise conv3x3 + silu -> u and u_transposed ----------------
// block per (b,d), 256 thr
__global__ void k3_conv(const float* __restrict__ cw, const float* __restrict__ cb){
    __shared__ float s_in[1024];
    __shared__ float s_u[1057];
    int bid = blockIdx.x;           // b*128+d
    int d = bid & 127;
    int tid = threadIdx.x;
    for(int i=tid;i<1024;i+=256) s_in[i]=g_x1[bid*Ln+i];
    float w9[9];
    #pragma unroll
    for(int j=0;j<9;j++) w9[j]=cw[d*9+j];
    float bias=cb[d];
    __syncthreads();
    #pragma unroll
    for(int r=0;r<4;r++){
        int i=tid+r*256;
        int h=i>>5, ww=i&31;
        float acc=bias;
        #pragma unroll
        for(int kh=0;kh<3;kh++){
            int hh=h+kh-1;
            if((unsigned)hh<32u){
                #pragma unroll
                for(int kw=0;kw<3;kw++){
                    int w2=ww+kw-1;
                    if((unsigned)w2<32u) acc=fmaf(s_in[hh*32+w2],w9[kh*3+kw],acc);
                }
            }
        }
        float v=acc/(1.f+__expf(-acc));
        g_u[bid*Ln+i]=v;
        s_u[i+(i>>5)]=v;
    }
    __syncthreads();
    #pragma unroll
    for(int r=0;r<4;r++){
        int t=tid+r*256;
        int l=trl(t);
        g_ut[bid*Ln+t]=s_u[l+(l>>5)];
    }
}

// ---------------- K4a: M[k,b,c,l] = sum_d x_proj_w[k,c,d] * u[b,d,l] ----------------
// grid (32,8), 128 thr, dyn smem = (4096 + 128*148)*4 = 92160 B
__global__ void k4a_proj(const float* __restrict__ xpw){
    extern __shared__ float sh[];
    float* shU  = sh;              // [128][32]
    float* shWt = sh + 4096;       // [128 d][148 pad] transposed
    int b  = blockIdx.y;
    int l0 = blockIdx.x*32;
    int tid = threadIdx.x;         // 128 threads
    for(int i=tid;i<144*128;i+=128){
        int kc=i>>7, d=i&127;
        shWt[d*148+kc]=xpw[i];
    }
    for(int i=tid;i<4096;i+=128){
        int d=i>>5, l=i&31;
        shU[i]=g_u[(b*DIn+d)*Ln + l0+l];
    }
    __syncthreads();
    int l = tid&31, k = tid>>5;
    float acc[36];
    #pragma unroll
    for(int j=0;j<36;j++) acc[j]=0.f;
    for(int c=0;c<128;c++){
        float xv=shU[c*32+l];
        const float* wp=&shWt[c*148 + k*36];
        #pragma unroll
        for(int j4=0;j4<9;j4++){
            float4 wv=*(const float4*)&wp[j4*4];
            acc[j4*4+0]=fmaf(wv.x,xv,acc[j4*4+0]);
            acc[j4*4+1]=fmaf(wv.y,xv,acc[j4*4+1]);
            acc[j4*4+2]=fmaf(wv.z,xv,acc[j4*4+2]);
            acc[j4*4+3]=fmaf(wv.w,xv,acc[j4*4+3]);
        }
    }
    int base=((k*Bn+b)*36)*Ln + l0+l;
    #pragma unroll
    for(int j=0;j<36;j++) g_M[base + j*Ln]=acc[j];
}

// ---------------- K4b: dt = softplus(dt_w @ M[:4] + dt_b), stored seq-time order ----------------
// block per (k,b,d) = 4096 blocks, 256 thr
__global__ void k4b_dt(const float* __restrict__ dtw, const float* __restrict__ dtb){
    __shared__ float s[1057];
    int kbd = blockIdx.x;
    int d = kbd&127, kb = kbd>>7, k = kb>>3;
    int tid=threadIdx.x;
    const float* Mr = g_M + kb*36*Ln;
    float w0=dtw[(k*DIn+d)*4+0], w1=dtw[(k*DIn+d)*4+1];
    float w2=dtw[(k*DIn+d)*4+2], w3=dtw[(k*DIn+d)*4+3];
    float bb=dtb[k*DIn+d];
    #pragma unroll
    for(int r=0;r<4;r++){
        int i=tid+r*256;
        float x=bb;
        x=fmaf(Mr[i],w0,x);
        x=fmaf(Mr[Ln+i],w1,x);
        x=fmaf(Mr[2*Ln+i],w2,x);
        x=fmaf(Mr[3*Ln+i],w3,x);
        float sp=(x>20.f)? x : __logf(1.f+__expf(x));
        s[i+(i>>5)]=sp;
    }
    __syncthreads();
    float* out = g_dt + kbd*Ln;
    #pragma unroll
    for(int r=0;r<4;r++){
        int t=tid+r*256;
        int l=pmap(k,t);
        out[t]=s[l+(l>>5)];
    }
}

// ---------------- K4c: B,C -> seq-time order (kb,t,n) ----------------
// grid (16 ltiles, 32 kb), 256 thr
__global__ void k4c_bc(){
    __shared__ float sB[64*17], sC[64*17];
    int kb=blockIdx.y, k=kb>>3;
    int l0=blockIdx.x*64;
    int tid=threadIdx.x;
    const float* MB = g_M + (kb*36+4)*Ln;
    const float* MCp= g_M + (kb*36+20)*Ln;
    #pragma unroll
    for(int r=0;r<4;r++){
        int i=tid+r*256;
        int n=i>>6, l=i&63;
        sB[l*17+n]=MB[n*Ln+l0+l];
        sC[l*17+n]=MCp[n*Ln+l0+l];
    }
    __syncthreads();
    #pragma unroll
    for(int r=0;r<4;r++){
        int i=tid+r*256;
        int l=i>>4, n=i&15;
        int ll=l0+l;
        int t;
        if(k==0) t=ll;
        else if(k==1) t=trl(ll);
        else if(k==2) t=1023-ll;
        else t=1023-trl(ll);
        int o=(kb*Ln+t)*Nn+n;
        g_Bt[o]=sB[l*17+n];
        g_Ct[o]=sC[l*17+n];
    }
}

// ---------------- K5: selective scan, smem-staged, double-buffered ----------------
// grid (8 dgrp, 4 k, 8 b), 256 thr
__global__ void __launch_bounds__(256) k5_scan(const float* __restrict__ Alogs,
                                               const float* __restrict__ Ds){
    __shared__ float sdt[2][1024], su[2][1024], sBs[2][1024], sCs[2][1024];
    __shared__ float sy[16*65];
    int tid=threadIdx.x;
    int n=tid&15, dd=tid>>4;
    int d0=blockIdx.x*16, k=blockIdx.y, b=blockIdx.z;
    int d=d0+dd;
    int kb=k*Bn+b;
    float A = -__expf(Alogs[(k*DIn+d)*Nn+n]);
    float Dsv = Ds[k*DIn+d];
    const float* dtg = g_dt + (kb*DIn+d0)*Ln;
    const float* ug  = ((k&1)? g_ut : g_u) + (b*DIn+d0)*Ln;
    const float* Bg  = g_Bt + kb*Ln*Nn;
    const float* Cg  = g_Ct + kb*Ln*Nn;
    int rev = (k&2);

    // stage chunk 0
    #pragma unroll
    for(int j=0;j<4;j++){
        int i=tid+j*256;
        int sd=i>>6, tl=i&63;
        sdt[0][i]=dtg[sd*Ln+tl];
        su [0][i]=ug [sd*Ln+(rev?1023-tl:tl)];
        sBs[0][i]=Bg[i];
        sCs[0][i]=Cg[i];
    }
    __syncthreads();
    float h=0.f;
    float rdt[4],ru[4],rB[4],rC[4];
    for(int ch=0;ch<16;ch++){
        int cur=ch&1, nxt=cur^1;
        int t0=ch*64;
        if(ch<15){
            int tn0=t0+64;
            #pragma unroll
            for(int j=0;j<4;j++){
                int i=tid+j*256;
                int sd=i>>6, tl=i&63;
                int t=tn0+tl;
                rdt[j]=dtg[sd*Ln+t];
                ru [j]=ug [sd*Ln+(rev?1023-t:t)];
                rB [j]=Bg[tn0*Nn+i];
                rC [j]=Cg[tn0*Nn+i];
            }
        }
        const float* pdt=&sdt[cur][dd*64];
        const float* pu =&su [cur][dd*64];
        const float* pB =&sBs[cur][0];
        const float* pC =&sCs[cur][0];
        #pragma unroll 4
        for(int tl=0;tl<64;tl++){
            float dtv=pdt[tl], uv=pu[tl];
            float Bv=pB[tl*16+n], Cv=pC[tl*16+n];
            float a=__expf(dtv*A);
            float du=dtv*uv;
            h=fmaf(h,a,du*Bv);
            float c=h*Cv;
            c += __shfl_xor_sync(0xffffffffu,c,8);
            c += __shfl_xor_sync(0xffffffffu,c,4);
            c += __shfl_xor_sync(0xffffffffu,c,2);
            c += __shfl_xor_sync(0xffffffffu,c,1);
            if(n==0) sy[dd*65+tl]=c+Dsv*uv;
        }
        __syncthreads();
        #pragma unroll
        for(int j=0;j<4;j++){
            int i=tid+j*256;
            int sd2=i&15, tl2=i>>4;
            int t=t0+tl2;
            int l=pmap(k,t);
            atomicAdd(&g_yP[(b*Ln+l)*DIn + d0+sd2], sy[sd2*65+tl2]);
        }
        if(ch<15){
            #pragma unroll
            for(int j=0;j<4;j++){
                int i=tid+j*256;
                sdt[nxt][i]=rdt[j];
                su [nxt][i]=ru[j];
                sBs[nxt][i]=rB[j];
                sCs[nxt][i]=rC[j];
            }
        }
        __syncthreads();
    }
}

// ---------------- K6: ln(y)*silu(z) -> out_proj -> +x -> ln -> mean ----------------
__global__ void k6_out(const float* __restrict__ ong, const float* __restrict__ onb,
                       const float* __restrict__ opw, const float* __restrict__ mg,
                       const float* __restrict__ mbb){
    __shared__ float sY[8*128];
    int tid=threadIdx.x, w=tid>>5, lane=tid&31;
    int pix=blockIdx.x*8+w;
    int b=pix>>10, l=pix&1023;
    float yv[4], zv[4];
    #pragma unroll
    for(int j=0;j<4;j++){
        int d=lane+32*j;
        yv[j]=g_yP[(b*Ln+l)*DIn+d];
        zv[j]=g_z [(b*Ln+l)*DIn+d];
    }
    float s=0.f,s2=0.f;
    #pragma unroll
    for(int j=0;j<4;j++){ s+=yv[j]; s2+=yv[j]*yv[j]; }
    #pragma unroll
    for(int off=16;off>0;off>>=1){
        s  += __shfl_xor_sync(0xffffffffu,s ,off);
        s2 += __shfl_xor_sync(0xffffffffu,s2,off);
    }
    float mean=s*(1.f/128.f);
    float var =s2*(1.f/128.f)-mean*mean;
    float rs=rsqrtf(var+EPSf);
    #pragma unroll
    for(int j=0;j<4;j++){
        int d=lane+32*j;
        float t=(yv[j]-mean)*rs*ong[d]+onb[d];
        float zz=zv[j];
        sY[w*128+d]=t*zz/(1.f+__expf(-zz));
    }
    __syncwarp();
    float a0=0.f,a1=0.f;
    for(int d2=0;d2<128;d2++){
        float yy=sY[w*128+d2];
        a0=fmaf(opw[ lane     *128+d2],yy,a0);
        a1=fmaf(opw[(lane+32)*128+d2],yy,a1);
    }
    const float* xr=g_x+(b*Ln+l)*MCn;
    float x0=xr[lane]+a0, x1v=xr[lane+32]+a1;
    float ss=x0+x1v, ss2=x0*x0+x1v*x1v;
    #pragma unroll
    for(int off=16;off>0;off>>=1){
        ss  += __shfl_xor_sync(0xffffffffu,ss ,off);
        ss2 += __shfl_xor_sync(0xffffffffu,ss2,off);
    }
    float m2=ss*(1.f/64.f);
    float v2=ss2*(1.f/64.f)-m2*m2;
    float rs2=rsqrtf(v2+EPSf);
    float v0=(x0 -m2)*rs2*mg[lane]   +mbb[lane];
    float v1=(x1v-m2)*rs2*mg[lane+32]+mbb[lane+32];
    atomicAdd(&g_zm[b*MCn+lane],    v0*(1.f/1024.f));
    atomicAdd(&g_zm[b*MCn+lane+32], v1*(1.f/1024.f));
}

// ---------------- K8: joint-embed MLP ----------------
__global__ void k8_fc(const float* __restrict__ w1,const float* __restrict__ g1,
                      const float* __restrict__ b1,const float* __restrict__ m1,
                      const float* __restrict__ v1,const float* __restrict__ w2){
    __shared__ float shH[64];
    int b=blockIdx.x, tid=threadIdx.x;
    if(tid<64){
        const float* wr=w1+tid*576;
        float a=0.f;
        for(int j=0;j<256;j++) a=fmaf(wr[j],     g_zr[b*256+j],a);
        for(int j=0;j<256;j++) a=fmaf(wr[256+j], g_zd[b*256+j],a);
        for(int j=0;j<64;j++)  a=fmaf(wr[512+j], g_zm[b*64+j],a);
        float h=(a-m1[tid])*rsqrtf(v1[tid]+EPSf)*g1[tid]+b1[tid];
        shH[tid]=h>0.f?h:0.f;
    }
    __syncthreads();
    for(int o=tid;o<512;o+=128){
        float a=0.f;
        const float* wr=w2+o*64;
        #pragma unroll
        for(int c=0;c<64;c++) a=fmaf(wr[c],shH[c],a);
        g_wgt[b*512+o]=1.f/(1.f+__expf(-a));
    }
}

// ---------------- K9: final reweighting ----------------
__global__ void k9_final(const float* __restrict__ rgb,const float* __restrict__ dem,
                         float* __restrict__ out){
    int idx=blockIdx.x*256+threadIdx.x;
    if(idx>=Bn*Cn*Ln) return;
    int c=(idx>>10)&255, b=idx>>18;
    float wrv=g_wgt[b*512+c], wdv=g_wgt[b*512+256+c];
    out[idx]=rgb[idx]*(1.f+wrv)+dem[idx]*(1.f+wdv);
}

// ---------------- launch ----------------
extern "C" void kernel_launch(void* const* d_in, const int* in_sizes, int n_in,
                              void* d_out, int out_size){
    const float* rgb   =(const float*)d_in[0];
    const float* dem   =(const float*)d_in[1];
    const float* wred  =(const float*)d_in[2];
    const float* bnr_g =(const float*)d_in[3];
    const float* bnr_b =(const float*)d_in[4];
    const float* bnr_m =(const float*)d_in[5];
    const float* bnr_v =(const float*)d_in[6];
    const float* ln1_g =(const float*)d_in[7];
    const float* ln1_b =(const float*)d_in[8];
    const float* ipw   =(const float*)d_in[9];
    const float* conv_w=(const float*)d_in[10];
    const float* conv_b=(const float*)d_in[11];
    const float* xpw   =(const float*)d_in[12];
    const float* dt_w  =(const float*)d_in[13];
    const float* dt_b  =(const float*)d_in[14];
    const float* Alogs =(const float*)d_in[15];
    const float* Ds    =(const float*)d_in[16];
    const float* on_g  =(const float*)d_in[17];
    const float* on_b  =(const float*)d_in[18];
    const float* opw   =(const float*)d_in[19];
    const float* mno_g =(const float*)d_in[20];
    const float* mno_b =(const float*)d_in[21];
    const float* je_w1 =(const float*)d_in[22];
    const float* bn1_g =(const float*)d_in[23];
    const float* bn1_b =(const float*)d_in[24];
    const float* bn1_m =(const float*)d_in[25];
    const float* bn1_v =(const float*)d_in[26];
    const float* je_w2 =(const float*)d_in[27];
    float* out=(float*)d_out;

    cudaFuncSetAttribute(k1_reduce, cudaFuncAttributeMaxDynamicSharedMemorySize, 98304);
    cudaFuncSetAttribute(k2_lnproj, cudaFuncAttributeMaxDynamicSharedMemorySize, 74240);
    cudaFuncSetAttribute(k4a_proj,  cudaFuncAttributeMaxDynamicSharedMemorySize, 92160);

    k7_means<<<512,256>>>(rgb,dem);
    k1_reduce<<<dim3(32,8),256,98304>>>(rgb,dem,wred,bnr_g,bnr_b,bnr_m,bnr_v);
    k2_lnproj<<<dim3(32,8),256,74240>>>(ln1_g,ln1_b,ipw);
    k3_conv<<<Bn*DIn,256>>>(conv_w,conv_b);
    k4a_proj<<<dim3(32,8),128,92160>>>(xpw);
    k4b_dt<<<Kn*Bn*DIn,256>>>(dt_w,dt_b);
    k4c_bc<<<dim3(16,32),256>>>();
    k5_scan<<<dim3(8,4,8),256>>>(Alogs,Ds);
    k6_out<<<1024,256>>>(on_g,on_b,opw,mno_g,mno_b);
    k8_fc<<<8,128>>>(je_w1,bn1_g,bn1_b,bn1_m,bn1_v,je_w2);
    k9_final<<<(Bn*Cn*Ln)/256,256>>>(rgb,dem,out);
}

// round 7
// speedup vs baseline: 2.6593x; 1.7610x over previous
#include <cuda_runtime.h>
#include <math.h>

#define Bn 8
#define Cn 256
#define Ln 1024
#define MCn 64
#define DIn 128
#define Kn 4
#define Nn 16
#define EPSf 1e-5f

// ---------------- scratch ----------------
__device__ float g_x [Bn*Ln*MCn];      // post-bn x, (b,l,o)
__device__ float g_z [Bn*Ln*DIn];      // gate z, (b,l,d)
__device__ float g_x1[Bn*DIn*Ln];      // pre-conv, (b,d,l)
__device__ float g_u [Bn*DIn*Ln];      // post conv+silu, (b,d,l)
__device__ float g_ut[Bn*DIn*Ln];      // transposed u: ut[t]=u[tr(t)]
__device__ float g_M [Kn*Bn*36*Ln];    // x_proj out, (k,b,c,l) spatial
__device__ float g_dt[Kn*Bn*DIn*Ln];   // softplus dt in SEQ-TIME order
__device__ float g_Bt[Kn*Bn*Ln*Nn];    // B in seq-time order, (kb,t,n)
__device__ float g_Ct[Kn*Bn*Ln*Nn];    // C in seq-time order
__device__ float g_yP[Bn*Ln*DIn];      // y pixel-major (b,l,d)
__device__ float g_zr[Bn*Cn];
__device__ float g_zd[Bn*Cn];
__device__ float g_zm[Bn*MCn];
__device__ float g_wgt[Bn*2*Cn];

__device__ __forceinline__ int trl(int l){ return ((l&31)<<5)|(l>>5); }
// l = p(k,t): spatial position of sequence step t
__device__ __forceinline__ int pmap(int k,int t){
    int tt=(k&2)?(1023-t):t;
    return (k&1)?trl(tt):tt;
}

// ---------------- K7: spatial means of rgb/dem + zero zm ----------------
__global__ void k7_means(const float* __restrict__ rgb, const float* __restrict__ dem){
    int gid = blockIdx.x*256+threadIdx.x;
    if(gid < Bn*MCn) g_zm[gid]=0.f;
    int gw = gid>>5;
    int lane=threadIdx.x&31;
    if(gw>=2*Bn*Cn) return;
    int which = (gw>=Bn*Cn);
    int bc = which ? gw-Bn*Cn : gw;
    const float* src=(which?dem:rgb)+bc*Ln;
    float s=0.f;
    for(int i=lane;i<Ln;i+=32) s+=src[i];
    #pragma unroll
    for(int off=16;off>0;off>>=1) s += __shfl_xor_sync(0xffffffffu,s,off);
    if(lane==0) (which?g_zd:g_zr)[bc]=s*(1.f/1024.f);
}

// ---------------- K1: x = bn(w_reduce @ (rgb+dem)) ----------------
__global__ void k1_reduce(const float* __restrict__ rgb, const float* __restrict__ dem,
                          const float* __restrict__ wr,  const float* __restrict__ bg,
                          const float* __restrict__ bb,  const float* __restrict__ bm,
                          const float* __restrict__ bv){
    extern __shared__ float sh[];
    float* shW = sh;              // [64][256]
    float* shX = sh + 64*256;     // [256][32]
    int b  = blockIdx.y;
    int l0 = blockIdx.x*32;
    int tid = threadIdx.x;
    for(int i=tid;i<64*256;i+=256) shW[i]=wr[i];
    for(int i=tid;i<256*32;i+=256){
        int c=i>>5, l=i&31;
        int gi=(b*Cn+c)*Ln + l0 + l;
        shX[i]=rgb[gi]+dem[gi];
    }
    __syncthreads();
    int l = tid & 31, o8 = tid>>5;
    float acc[8]={0,0,0,0,0,0,0,0};
    for(int c=0;c<256;c++){
        float xv = shX[c*32+l];
        #pragma unroll
        for(int j=0;j<8;j++) acc[j]=fmaf(shW[(o8*8+j)*256+c],xv,acc[j]);
    }
    #pragma unroll
    for(int j=0;j<8;j++){
        int o=o8*8+j;
        float v=(acc[j]-bm[o])*rsqrtf(bv[o]+EPSf)*bg[o]+bb[o];
        g_x[(b*Ln+l0+l)*MCn + o]=v;
    }
}

// ---------------- K2: ln1 + in_proj -> x1, z ; zero yP ----------------
// grid (32,8), 256 thr, dyn smem = (16384 + 32*68)*4 = 74240 B
__global__ void k2_lnproj(const float* __restrict__ lg, const float* __restrict__ lb,
                          const float* __restrict__ ipw){
    extern __shared__ float sh[];
    float* shW  = sh;             // [256][64]
    float* shXn = sh + 16384;     // [32][68]
    int b  = blockIdx.y;
    int l0 = blockIdx.x*32;
    int tid = threadIdx.x;
    for(int i=tid;i<16384;i+=256) shW[i]=ipw[i];
    for(int i=tid;i<32*128;i+=256) g_yP[(b*Ln+l0)*DIn + i]=0.f;
    int w = tid>>5, lane = tid&31;
    #pragma unroll
    for(int pp=0;pp<4;pp++){
        int p=w*4+pp;
        const float* xr = g_x + (b*Ln + l0+p)*MCn;
        float v0=xr[lane], v1=xr[lane+32];
        float s=v0+v1, s2=v0*v0+v1*v1;
        #pragma unroll
        for(int off=16;off>0;off>>=1){
            s  += __shfl_xor_sync(0xffffffffu,s ,off);
            s2 += __shfl_xor_sync(0xffffffffu,s2,off);
        }
        float mean=s*(1.f/64.f);
        float var =s2*(1.f/64.f)-mean*mean;
        float rs=rsqrtf(var+EPSf);
        shXn[p*68+lane]    =(v0-mean)*rs*lg[lane]   +lb[lane];
        shXn[p*68+lane+32] =(v1-mean)*rs*lg[lane+32]+lb[lane+32];
    }
    __syncthreads();
    int og = tid>>4, pl = tid&15;
    float acc0[16], acc1[16];
    #pragma unroll
    for(int j=0;j<16;j++){ acc0[j]=0.f; acc1[j]=0.f; }
    for(int c=0;c<64;c+=4){
        float4 xa=*(float4*)&shXn[pl*68+c];
        float4 xb=*(float4*)&shXn[(pl+16)*68+c];
        #pragma unroll
        for(int j=0;j<16;j++){
            float4 wv=*(float4*)&shW[(og*16+j)*64+c];
            float t0=fmaf(wv.x,xa.x,fmaf(wv.y,xa.y,fmaf(wv.z,xa.z,wv.w*xa.w)));
            float t1=fmaf(wv.x,xb.x,fmaf(wv.y,xb.y,fmaf(wv.z,xb.z,wv.w*xb.w)));
            acc0[j]+=t0; acc1[j]+=t1;
        }
    }
    __syncthreads();   // shW free now
    float* zb = sh;    // [32][128]
    if(og<8){
        #pragma unroll
        for(int j=0;j<16;j++){
            int o=og*16+j;
            g_x1[(b*DIn+o)*Ln + l0+pl]   = acc0[j];
            g_x1[(b*DIn+o)*Ln + l0+pl+16]= acc1[j];
        }
    } else {
        #pragma unroll
        for(int j=0;j<16;j++){
            int dz=(og-8)*16+j;
            zb[pl*128+dz]     = acc0[j];
            zb[(pl+16)*128+dz]= acc1[j];
        }
    }
    __syncthreads();
    for(int i=tid;i<32*128;i+=256) g_z[(b*Ln+l0)*DIn + i]=zb[i];
}

// ---------------- K3: depthwise conv3x3 + silu -> u and u_transposed ----------------
// block per (b,d), 256 thr
__global__ void k3_conv(const float* __restrict__ cw, const float* __restrict__ cb){
    __shared__ float s_in[1024];
    __shared__ float s_u[1057];
    int bid = blockIdx.x;           // b*128+d
    int d = bid & 127;
    int tid = threadIdx.x;
    for(int i=tid;i<1024;i+=256) s_in[i]=g_x1[bid*Ln+i];
    float w9[9];
    #pragma unroll
    for(int j=0;j<9;j++) w9[j]=cw[d*9+j];
    float bias=cb[d];
    __syncthreads();
    #pragma unroll
    for(int r=0;r<4;r++){
        int i=tid+r*256;
        int h=i>>5, ww=i&31;
        float acc=bias;
        #pragma unroll
        for(int kh=0;kh<3;kh++){
            int hh=h+kh-1;
            if((unsigned)hh<32u){
                #pragma unroll
                for(int kw=0;kw<3;kw++){
                    int w2=ww+kw-1;
                    if((unsigned)w2<32u) acc=fmaf(s_in[hh*32+w2],w9[kh*3+kw],acc);
                }
            }
        }
        float v=acc/(1.f+__expf(-acc));
        g_u[bid*Ln+i]=v;
        s_u[i+(i>>5)]=v;
    }
    __syncthreads();
    #pragma unroll
    for(int r=0;r<4;r++){
        int t=tid+r*256;
        int l=trl(t);
        g_ut[bid*Ln+t]=s_u[l+(l>>5)];
    }
}

// ---------------- K4a: M[k,b,c,l] = sum_d x_proj_w[k,c,d] * u[b,d,l] ----------------
// grid (32,8), 128 thr, dyn smem = (4096 + 128*148)*4 = 92160 B
__global__ void k4a_proj(const float* __restrict__ xpw){
    extern __shared__ float sh[];
    float* shU  = sh;              // [128][32]
    float* shWt = sh + 4096;       // [128 d][148 pad] transposed
    int b  = blockIdx.y;
    int l0 = blockIdx.x*32;
    int tid = threadIdx.x;         // 128 threads
    for(int i=tid;i<144*128;i+=128){
        int kc=i>>7, d=i&127;
        shWt[d*148+kc]=xpw[i];
    }
    for(int i=tid;i<4096;i+=128){
        int d=i>>5, l=i&31;
        shU[i]=g_u[(b*DIn+d)*Ln + l0+l];
    }
    __syncthreads();
    int l = tid&31, k = tid>>5;
    float acc[36];
    #pragma unroll
    for(int j=0;j<36;j++) acc[j]=0.f;
    for(int c=0;c<128;c++){
        float xv=shU[c*32+l];
        const float* wp=&shWt[c*148 + k*36];
        #pragma unroll
        for(int j4=0;j4<9;j4++){
            float4 wv=*(const float4*)&wp[j4*4];
            acc[j4*4+0]=fmaf(wv.x,xv,acc[j4*4+0]);
            acc[j4*4+1]=fmaf(wv.y,xv,acc[j4*4+1]);
            acc[j4*4+2]=fmaf(wv.z,xv,acc[j4*4+2]);
            acc[j4*4+3]=fmaf(wv.w,xv,acc[j4*4+3]);
        }
    }
    int base=((k*Bn+b)*36)*Ln + l0+l;
    #pragma unroll
    for(int j=0;j<36;j++) g_M[base + j*Ln]=acc[j];
}

// ---------------- K4b: dt = softplus(dt_w @ M[:4] + dt_b), stored seq-time order ----------------
// block per (k,b,d) = 4096 blocks, 256 thr
__global__ void k4b_dt(const float* __restrict__ dtw, const float* __restrict__ dtb){
    __shared__ float s[1057];
    int kbd = blockIdx.x;
    int d = kbd&127, kb = kbd>>7, k = kb>>3;
    int tid=threadIdx.x;
    const float* Mr = g_M + kb*36*Ln;
    float w0=dtw[(k*DIn+d)*4+0], w1=dtw[(k*DIn+d)*4+1];
    float w2=dtw[(k*DIn+d)*4+2], w3=dtw[(k*DIn+d)*4+3];
    float bb=dtb[k*DIn+d];
    #pragma unroll
    for(int r=0;r<4;r++){
        int i=tid+r*256;
        float x=bb;
        x=fmaf(Mr[i],w0,x);
        x=fmaf(Mr[Ln+i],w1,x);
        x=fmaf(Mr[2*Ln+i],w2,x);
        x=fmaf(Mr[3*Ln+i],w3,x);
        float sp=(x>20.f)? x : __logf(1.f+__expf(x));
        s[i+(i>>5)]=sp;
    }
    __syncthreads();
    float* out = g_dt + kbd*Ln;
    #pragma unroll
    for(int r=0;r<4;r++){
        int t=tid+r*256;
        int l=pmap(k,t);
        out[t]=s[l+(l>>5)];
    }
}

// ---------------- K4c: B,C -> seq-time order (kb,t,n) ----------------
// grid (16 ltiles, 32 kb), 256 thr
__global__ void k4c_bc(){
    __shared__ float sB[64*17], sC[64*17];
    int kb=blockIdx.y, k=kb>>3;
    int l0=blockIdx.x*64;
    int tid=threadIdx.x;
    const float* MB = g_M + (kb*36+4)*Ln;
    const float* MCp= g_M + (kb*36+20)*Ln;
    #pragma unroll
    for(int r=0;r<4;r++){
        int i=tid+r*256;
        int n=i>>6, l=i&63;
        sB[l*17+n]=MB[n*Ln+l0+l];
        sC[l*17+n]=MCp[n*Ln+l0+l];
    }
    __syncthreads();
    #pragma unroll
    for(int r=0;r<4;r++){
        int i=tid+r*256;
        int l=i>>4, n=i&15;
        int ll=l0+l;
        int t;
        if(k==0) t=ll;
        else if(k==1) t=trl(ll);
        else if(k==2) t=1023-ll;
        else t=1023-trl(ll);
        int o=(kb*Ln+t)*Nn+n;
        g_Bt[o]=sB[l*17+n];
        g_Ct[o]=sC[l*17+n];
    }
}

// ---------------- K5: selective scan, smem-staged, double-buffered ----------------
// grid (8 dgrp, 4 k, 8 b), 256 thr
__global__ void __launch_bounds__(256) k5_scan(const float* __restrict__ Alogs,
                                               const float* __restrict__ Ds){
    __shared__ float sdt[2][1024], su[2][1024], sBs[2][1024], sCs[2][1024];
    __shared__ float sy[16*65];
    int tid=threadIdx.x;
    int n=tid&15, dd=tid>>4;
    int d0=blockIdx.x*16, k=blockIdx.y, b=blockIdx.z;
    int d=d0+dd;
    int kb=k*Bn+b;
    float A = -__expf(Alogs[(k*DIn+d)*Nn+n]);
    float Dsv = Ds[k*DIn+d];
    const float* dtg = g_dt + (kb*DIn+d0)*Ln;
    const float* ug  = ((k&1)? g_ut : g_u) + (b*DIn+d0)*Ln;
    const float* Bg  = g_Bt + kb*Ln*Nn;
    const float* Cg  = g_Ct + kb*Ln*Nn;
    int rev = (k&2);

    // stage chunk 0
    #pragma unroll
    for(int j=0;j<4;j++){
        int i=tid+j*256;
        int sd=i>>6, tl=i&63;
        sdt[0][i]=dtg[sd*Ln+tl];
        su [0][i]=ug [sd*Ln+(rev?1023-tl:tl)];
        sBs[0][i]=Bg[i];
        sCs[0][i]=Cg[i];
    }
    __syncthreads();
    float h=0.f;
    float rdt[4],ru[4],rB[4],rC[4];
    for(int ch=0;ch<16;ch++){
        int cur=ch&1, nxt=cur^1;
        int t0=ch*64;
        if(ch<15){
            int tn0=t0+64;
            #pragma unroll
            for(int j=0;j<4;j++){
                int i=tid+j*256;
                int sd=i>>6, tl=i&63;
                int t=tn0+tl;
                rdt[j]=dtg[sd*Ln+t];
                ru [j]=ug [sd*Ln+(rev?1023-t:t)];
                rB [j]=Bg[tn0*Nn+i];
                rC [j]=Cg[tn0*Nn+i];
            }
        }
        const float* pdt=&sdt[cur][dd*64];
        const float* pu =&su [cur][dd*64];
        const float* pB =&sBs[cur][0];
        const float* pC =&sCs[cur][0];
        #pragma unroll 4
        for(int tl=0;tl<64;tl++){
            float dtv=pdt[tl], uv=pu[tl];
            float Bv=pB[tl*16+n], Cv=pC[tl*16+n];
            float a=__expf(dtv*A);
            float du=dtv*uv;
            h=fmaf(h,a,du*Bv);
            float c=h*Cv;
            c += __shfl_xor_sync(0xffffffffu,c,8);
            c += __shfl_xor_sync(0xffffffffu,c,4);
            c += __shfl_xor_sync(0xffffffffu,c,2);
            c += __shfl_xor_sync(0xffffffffu,c,1);
            if(n==0) sy[dd*65+tl]=c+Dsv*uv;
        }
        __syncthreads();
        #pragma unroll
        for(int j=0;j<4;j++){
            int i=tid+j*256;
            int sd2=i&15, tl2=i>>4;
            int t=t0+tl2;
            int l=pmap(k,t);
            atomicAdd(&g_yP[(b*Ln+l)*DIn + d0+sd2], sy[sd2*65+tl2]);
        }
        if(ch<15){
            #pragma unroll
            for(int j=0;j<4;j++){
                int i=tid+j*256;
                sdt[nxt][i]=rdt[j];
                su [nxt][i]=ru[j];
                sBs[nxt][i]=rB[j];
                sCs[nxt][i]=rC[j];
            }
        }
        __syncthreads();
    }
}

// ---------------- K6: ln(y)*silu(z) -> out_proj -> +x -> ln -> mean ----------------
// grid 256, 256 thr; opw staged TRANSPOSED in smem; 4 pixels per warp
__global__ void __launch_bounds__(256) k6_out(const float* __restrict__ ong, const float* __restrict__ onb,
                       const float* __restrict__ opw, const float* __restrict__ mg,
                       const float* __restrict__ mbb){
    __shared__ float sW[128*65];   // sW[d2*65+o] = opw[o*128+d2]
    __shared__ float sY[8*132];
    int tid=threadIdx.x, w=tid>>5, lane=tid&31;
    for(int i=tid;i<MCn*DIn;i+=256){
        int o=i>>7, d2=i&127;
        sW[d2*65+o]=opw[i];
    }
    __syncthreads();
    float g0=ong[lane], g1=ong[lane+32], g2=ong[lane+64], g3=ong[lane+96];
    float o0=onb[lane], o1=onb[lane+32], o2=onb[lane+64], o3=onb[lane+96];
    float mgl=mg[lane], mgh=mg[lane+32], mbl=mbb[lane], mbh=mbb[lane+32];
    #pragma unroll
    for(int pp=0;pp<4;pp++){
        int pix=blockIdx.x*32 + w*4 + pp;
        int b=pix>>10, l=pix&1023;
        float yv[4], zv[4];
        #pragma unroll
        for(int j=0;j<4;j++){
            int d=lane+32*j;
            yv[j]=g_yP[(b*Ln+l)*DIn+d];
            zv[j]=g_z [(b*Ln+l)*DIn+d];
        }
        float s=0.f,s2=0.f;
        #pragma unroll
        for(int j=0;j<4;j++){ s+=yv[j]; s2+=yv[j]*yv[j]; }
        #pragma unroll
        for(int off=16;off>0;off>>=1){
            s  += __shfl_xor_sync(0xffffffffu,s ,off);
            s2 += __shfl_xor_sync(0xffffffffu,s2,off);
        }
        float mean=s*(1.f/128.f);
        float var =s2*(1.f/128.f)-mean*mean;
        float rs=rsqrtf(var+EPSf);
        float gg[4]={g0,g1,g2,g3}, ob[4]={o0,o1,o2,o3};
        #pragma unroll
        for(int j=0;j<4;j++){
            int d=lane+32*j;
            float t=(yv[j]-mean)*rs*gg[j]+ob[j];
            float zz=zv[j];
            sY[w*132+d]=t*zz/(1.f+__expf(-zz));
        }
        __syncwarp();
        float a0=0.f,a1=0.f;
        #pragma unroll 4
        for(int d2=0;d2<128;d2++){
            float yy=sY[w*132+d2];
            a0=fmaf(sW[d2*65+lane],   yy,a0);
            a1=fmaf(sW[d2*65+lane+32],yy,a1);
        }
        const float* xr=g_x+(b*Ln+l)*MCn;
        float x0=xr[lane]+a0, x1v=xr[lane+32]+a1;
        float ss=x0+x1v, ss2=x0*x0+x1v*x1v;
        #pragma unroll
        for(int off=16;off>0;off>>=1){
            ss  += __shfl_xor_sync(0xffffffffu,ss ,off);
            ss2 += __shfl_xor_sync(0xffffffffu,ss2,off);
        }
        float m2=ss*(1.f/64.f);
        float v2=ss2*(1.f/64.f)-m2*m2;
        float rs2=rsqrtf(v2+EPSf);
        float v0=(x0 -m2)*rs2*mgl+mbl;
        float v1=(x1v-m2)*rs2*mgh+mbh;
        atomicAdd(&g_zm[b*MCn+lane],    v0*(1.f/1024.f));
        atomicAdd(&g_zm[b*MCn+lane+32], v1*(1.f/1024.f));
    }
}

// ---------------- K8: joint-embed MLP ----------------
__global__ void k8_fc(const float* __restrict__ w1,const float* __restrict__ g1,
                      const float* __restrict__ b1,const float* __restrict__ m1,
                      const float* __restrict__ v1,const float* __restrict__ w2){
    __shared__ float shH[64];
    int b=blockIdx.x, tid=threadIdx.x;
    if(tid<64){
        const float* wr=w1+tid*576;
        float a=0.f;
        for(int j=0;j<256;j++) a=fmaf(wr[j],     g_zr[b*256+j],a);
        for(int j=0;j<256;j++) a=fmaf(wr[256+j], g_zd[b*256+j],a);
        for(int j=0;j<64;j++)  a=fmaf(wr[512+j], g_zm[b*64+j],a);
        float h=(a-m1[tid])*rsqrtf(v1[tid]+EPSf)*g1[tid]+b1[tid];
        shH[tid]=h>0.f?h:0.f;
    }
    __syncthreads();
    for(int o=tid;o<512;o+=128){
        float a=0.f;
        const float* wr=w2+o*64;
        #pragma unroll
        for(int c=0;c<64;c++) a=fmaf(wr[c],shH[c],a);
        g_wgt[b*512+o]=1.f/(1.f+__expf(-a));
    }
}

// ---------------- K9: final reweighting ----------------
__global__ void k9_final(const float* __restrict__ rgb,const float* __restrict__ dem,
                         float* __restrict__ out){
    int idx=blockIdx.x*256+threadIdx.x;
    if(idx>=Bn*Cn*Ln) return;
    int c=(idx>>10)&255, b=idx>>18;
    float wrv=g_wgt[b*512+c], wdv=g_wgt[b*512+256+c];
    out[idx]=rgb[idx]*(1.f+wrv)+dem[idx]*(1.f+wdv);
}

// ---------------- launch ----------------
extern "C" void kernel_launch(void* const* d_in, const int* in_sizes, int n_in,
                              void* d_out, int out_size){
    const float* rgb   =(const float*)d_in[0];
    const float* dem   =(const float*)d_in[1];
    const float* wred  =(const float*)d_in[2];
    const float* bnr_g =(const float*)d_in[3];
    const float* bnr_b =(const float*)d_in[4];
    const float* bnr_m =(const float*)d_in[5];
    const float* bnr_v =(const float*)d_in[6];
    const float* ln1_g =(const float*)d_in[7];
    const float* ln1_b =(const float*)d_in[8];
    const float* ipw   =(const float*)d_in[9];
    const float* conv_w=(const float*)d_in[10];
    const float* conv_b=(const float*)d_in[11];
    const float* xpw   =(const float*)d_in[12];
    const float* dt_w  =(const float*)d_in[13];
    const float* dt_b  =(const float*)d_in[14];
    const float* Alogs =(const float*)d_in[15];
    const float* Ds    =(const float*)d_in[16];
    const float* on_g  =(const float*)d_in[17];
    const float* on_b  =(const float*)d_in[18];
    const float* opw   =(const float*)d_in[19];
    const float* mno_g =(const float*)d_in[20];
    const float* mno_b =(const float*)d_in[21];
    const float* je_w1 =(const float*)d_in[22];
    const float* bn1_g =(const float*)d_in[23];
    const float* bn1_b =(const float*)d_in[24];
    const float* bn1_m =(const float*)d_in[25];
    const float* bn1_v =(const float*)d_in[26];
    const float* je_w2 =(const float*)d_in[27];
    float* out=(float*)d_out;

    cudaFuncSetAttribute(k1_reduce, cudaFuncAttributeMaxDynamicSharedMemorySize, 98304);
    cudaFuncSetAttribute(k2_lnproj, cudaFuncAttributeMaxDynamicSharedMemorySize, 74240);
    cudaFuncSetAttribute(k4a_proj,  cudaFuncAttributeMaxDynamicSharedMemorySize, 92160);

    k7_means<<<512,256>>>(rgb,dem);
    k1_reduce<<<dim3(32,8),256,98304>>>(rgb,dem,wred,bnr_g,bnr_b,bnr_m,bnr_v);
    k2_lnproj<<<dim3(32,8),256,74240>>>(ln1_g,ln1_b,ipw);
    k3_conv<<<Bn*DIn,256>>>(conv_w,conv_b);
    k4a_proj<<<dim3(32,8),128,92160>>>(xpw);
    k4b_dt<<<Kn*Bn*DIn,256>>>(dt_w,dt_b);
    k4c_bc<<<dim3(16,32),256>>>();
    k5_scan<<<dim3(8,4,8),256>>>(Alogs,Ds);
    k6_out<<<256,256>>>(on_g,on_b,opw,mno_g,mno_b);
    k8_fc<<<8,128>>>(je_w1,bn1_g,bn1_b,bn1_m,bn1_v,je_w2);
    k9_final<<<(Bn*Cn*Ln)/256,256>>>(rgb,dem,out);
}